// round 4
// baseline (speedup 1.0000x reference)
#include <cuda_runtime.h>

#define BW    512      // batch windows
#define NTOK  512      // query tokens per window
#define DIMC  192
#define NH    6
#define HD    32
#define PT    64       // permuted kv tokens per window
#define QSCALE 0.17677669529663687f   // 1/sqrt(32)

// ---------------- scratch (static device globals; no runtime allocation) ----
__device__ float g_q[(size_t)BW * NH * NTOK * HD];    // [b][h][n][d]
__device__ float g_k[(size_t)BW * NH * PT * HD];      // [b][h][p][d]
__device__ float g_v[(size_t)BW * NH * PT * HD];      // [b][h][p][d]
__device__ float g_bias[NH * NTOK * PT];              // [h][n][p]
__device__ float g_att[(size_t)BW * NTOK * DIMC];     // [b][n][h*32+d]

// ---------------- kernel 0: gather relative-position bias -------------------
__global__ void bias_gather(const float* __restrict__ table,
                            const int* __restrict__ rpi) {
    int idx = blockIdx.x * 256 + threadIdx.x;
    if (idx >= NH * NTOK * PT) return;
    int h = idx / (NTOK * PT);
    int r = idx - h * (NTOK * PT);            // n*64 + p
    g_bias[idx] = table[rpi[r] * NH + h];
}

// ---------------- kernel 1: fused QKV projection + permuted scatter ---------
// y[262144 x 240] = x[262144 x 192] @ [wq | wkv]; block tile 128x48, thread 8x3
__global__ __launch_bounds__(256) void qkv_gemm(
    const float* __restrict__ x,
    const float* __restrict__ wq, const float* __restrict__ bq,
    const float* __restrict__ wkv, const float* __restrict__ bkv)
{
    __shared__ float w_sh[192 * 48];     // [k][j], full K resident
    __shared__ float x_sh[128 * 17];     // [r][kk], pad 17 for conflict-free
    int tid = threadIdx.x;
    int ty = tid >> 4, tx = tid & 15;
    int row0 = blockIdx.x * 128;
    int col0 = blockIdx.y * 48;

    for (int i = tid; i < 192 * 48; i += 256) {
        int k = i / 48, j = i - k * 48;
        int c = col0 + j;
        w_sh[i] = (c < 192) ? wq[k * 192 + c] : wkv[k * 48 + (c - 192)];
    }

    float acc[8][3];
#pragma unroll
    for (int i = 0; i < 8; i++)
#pragma unroll
        for (int j = 0; j < 3; j++) acc[i][j] = 0.f;

    for (int k0 = 0; k0 < 192; k0 += 16) {
        __syncthreads();
#pragma unroll
        for (int l = 0; l < 2; l++) {
            int f = tid * 2 + l;                 // 0..511
            int r = f >> 2, c4 = (f & 3) * 4;
            float4 xv = *(const float4*)(x + (size_t)(row0 + r) * 192 + k0 + c4);
            x_sh[r * 17 + c4 + 0] = xv.x;
            x_sh[r * 17 + c4 + 1] = xv.y;
            x_sh[r * 17 + c4 + 2] = xv.z;
            x_sh[r * 17 + c4 + 3] = xv.w;
        }
        __syncthreads();
#pragma unroll
        for (int kk = 0; kk < 16; kk++) {
            float a[8], bb[3];
#pragma unroll
            for (int i = 0; i < 8; i++) a[i] = x_sh[(ty * 8 + i) * 17 + kk];
#pragma unroll
            for (int j = 0; j < 3; j++) bb[j] = w_sh[(k0 + kk) * 48 + tx * 3 + j];
#pragma unroll
            for (int i = 0; i < 8; i++)
#pragma unroll
                for (int j = 0; j < 3; j++)
                    acc[i][j] = fmaf(a[i], bb[j], acc[i][j]);
        }
    }

#pragma unroll
    for (int i = 0; i < 8; i++) {
        int row = row0 + ty * 8 + i;
        int b = row >> 9, n = row & 511;
#pragma unroll
        for (int j = 0; j < 3; j++) {
            int c = col0 + tx * 3 + j;
            float v = acc[i][j];
            if (c < 192) {                       // Q path
                v = (v + bq[c]) * QSCALE;
                int head = c >> 5, d = c & 31;
                g_q[(((size_t)b * NH + head) * NTOK + n) * HD + d] = v;
            } else {                             // KV path: permuted scatter
                int c4 = c - 192;
                v = v + bkv[c4];
                int D = n >> 6, H = (n >> 3) & 7, W = n & 7;
                int p  = ((D >> 1) << 4) + ((H >> 1) << 2) + (W >> 1);
                int c2 = (H & 1) * 96 + (W & 1) * 48 + c4;
                int head = c2 >> 5, d = c2 & 31;
                size_t dst = (((size_t)b * NH + head) * PT + p) * HD + d;
                if ((D & 1) == 0) g_k[dst] = v;
                else              g_v[dst] = v;
            }
        }
    }
}

// ---------------- kernel 2: attention (1 thread = 1 query row) --------------
__global__ __launch_bounds__(128) void attn_kernel() {
    int bh = blockIdx.x;                 // b*6 + h
    int h  = bh % NH;
    int b  = bh / NH;
    int n  = blockIdx.y * 128 + threadIdx.x;

    __shared__ float4 k4[PT * 8];
    __shared__ float4 v4[PT * 8];
    const float4* gk = (const float4*)(g_k + (size_t)bh * PT * HD);
    const float4* gv = (const float4*)(g_v + (size_t)bh * PT * HD);
    for (int i = threadIdx.x; i < PT * 8; i += 128) { k4[i] = gk[i]; v4[i] = gv[i]; }

    float4 q[8];
    const float4* gq = (const float4*)(g_q + ((size_t)bh * NTOK + n) * HD);
#pragma unroll
    for (int i = 0; i < 8; i++) q[i] = gq[i];

    float sc[64];
    const float4* brow = (const float4*)(g_bias + ((size_t)h * NTOK + n) * PT);
#pragma unroll
    for (int i = 0; i < 16; i++) {
        float4 bb = brow[i];
        sc[4 * i + 0] = bb.x; sc[4 * i + 1] = bb.y;
        sc[4 * i + 2] = bb.z; sc[4 * i + 3] = bb.w;
    }
    __syncthreads();

    float m = -1e30f;
#pragma unroll
    for (int p = 0; p < 64; p++) {
        float s = sc[p];
#pragma unroll
        for (int d = 0; d < 8; d++) {
            float4 kk = k4[p * 8 + d];           // broadcast LDS.128
            s += q[d].x * kk.x + q[d].y * kk.y + q[d].z * kk.z + q[d].w * kk.w;
        }
        sc[p] = s;
        m = fmaxf(m, s);
    }
    float sum = 0.f;
#pragma unroll
    for (int p = 0; p < 64; p++) { float e = __expf(sc[p] - m); sc[p] = e; sum += e; }

    float4 acc[8];
#pragma unroll
    for (int d = 0; d < 8; d++) acc[d] = make_float4(0.f, 0.f, 0.f, 0.f);
#pragma unroll
    for (int p = 0; p < 64; p++) {
        float pr = sc[p];
#pragma unroll
        for (int d = 0; d < 8; d++) {
            float4 vv = v4[p * 8 + d];           // broadcast LDS.128
            acc[d].x = fmaf(pr, vv.x, acc[d].x);
            acc[d].y = fmaf(pr, vv.y, acc[d].y);
            acc[d].z = fmaf(pr, vv.z, acc[d].z);
            acc[d].w = fmaf(pr, vv.w, acc[d].w);
        }
    }
    float inv = 1.f / sum;
    float4* orow = (float4*)(g_att + ((size_t)(b * NTOK + n)) * DIMC + h * HD);
#pragma unroll
    for (int d = 0; d < 8; d++) {
        acc[d].x *= inv; acc[d].y *= inv; acc[d].z *= inv; acc[d].w *= inv;
        orow[d] = acc[d];
    }
}

// ---------------- kernel 3: output projection -------------------------------
__global__ __launch_bounds__(256) void proj_gemm(
    const float* __restrict__ wproj, const float* __restrict__ bproj,
    float* __restrict__ out)
{
    __shared__ float w_sh[192 * 48];
    __shared__ float x_sh[128 * 17];
    int tid = threadIdx.x;
    int ty = tid >> 4, tx = tid & 15;
    int row0 = blockIdx.x * 128;
    int col0 = blockIdx.y * 48;

    for (int i = tid; i < 192 * 48; i += 256) {
        int k = i / 48, j = i - k * 48;
        w_sh[i] = wproj[k * 192 + col0 + j];
    }

    float acc[8][3];
#pragma unroll
    for (int i = 0; i < 8; i++)
#pragma unroll
        for (int j = 0; j < 3; j++) acc[i][j] = 0.f;

    for (int k0 = 0; k0 < 192; k0 += 16) {
        __syncthreads();
#pragma unroll
        for (int l = 0; l < 2; l++) {
            int f = tid * 2 + l;
            int r = f >> 2, c4 = (f & 3) * 4;
            float4 xv = *(const float4*)(g_att + (size_t)(row0 + r) * 192 + k0 + c4);
            x_sh[r * 17 + c4 + 0] = xv.x;
            x_sh[r * 17 + c4 + 1] = xv.y;
            x_sh[r * 17 + c4 + 2] = xv.z;
            x_sh[r * 17 + c4 + 3] = xv.w;
        }
        __syncthreads();
#pragma unroll
        for (int kk = 0; kk < 16; kk++) {
            float a[8], bb[3];
#pragma unroll
            for (int i = 0; i < 8; i++) a[i] = x_sh[(ty * 8 + i) * 17 + kk];
#pragma unroll
            for (int j = 0; j < 3; j++) bb[j] = w_sh[(k0 + kk) * 48 + tx * 3 + j];
#pragma unroll
            for (int i = 0; i < 8; i++)
#pragma unroll
                for (int j = 0; j < 3; j++)
                    acc[i][j] = fmaf(a[i], bb[j], acc[i][j]);
        }
    }

#pragma unroll
    for (int i = 0; i < 8; i++) {
        size_t row = row0 + ty * 8 + i;
#pragma unroll
        for (int j = 0; j < 3; j++) {
            int c = col0 + tx * 3 + j;
            out[row * DIMC + c] = acc[i][j] + bproj[c];
        }
    }
}

// ---------------- launch ----------------------------------------------------
extern "C" void kernel_launch(void* const* d_in, const int* in_sizes, int n_in,
                              void* d_out, int out_size) {
    const float* x     = (const float*)d_in[0];
    const float* wq    = (const float*)d_in[1];
    const float* bq    = (const float*)d_in[2];
    const float* wkv   = (const float*)d_in[3];
    const float* bkv   = (const float*)d_in[4];
    const float* table = (const float*)d_in[5];
    const float* wproj = (const float*)d_in[6];
    const float* bproj = (const float*)d_in[7];
    const int*   rpi   = (const int*)d_in[8];
    float* out = (float*)d_out;

    bias_gather<<<(NH * NTOK * PT + 255) / 256, 256>>>(table, rpi);
    qkv_gemm<<<dim3(2048, 5), 256>>>(x, wq, bq, wkv, bkv);
    attn_kernel<<<dim3(BW * NH, 4), 128>>>();
    proj_gemm<<<dim3(2048, 4), 256>>>(wproj, bproj, out);
}